// round 8
// baseline (speedup 1.0000x reference)
#include <cuda_runtime.h>

#define BB 16
#define TT 128
#define DD 1024
#define EE 128
#define HHN 128
#define GG 384           // 3*H
#define NSEQ (BB*TT)     // 2048
#define NTASK 128        // one task per time position i (16 batches each)

// scan smem layout (floats)
// [0, 24576): r,z weight pairs (12 of 16 per qt) as ull2-interleaved (96KB)
#define OFF_SH2   24576                 // 16*132 hidden states
#define OFF_PA    (OFF_SH2 + 16*132)    // group A partials 4*8*3*128
#define OFF_PB    (OFF_PA + 12288)      // group B partials
#define SMEM_FLOATS (OFF_PB + 12288)    // 51264 floats = 205056 B

// ---------------- scratch (device globals; no allocation) ----------------
__device__ float g_emb [NSEQ*EE];
__device__ float g_wemb[NSEQ*EE];       // Wo[e]*emb
__device__ float g_GXa [NSEQ*GG];
__device__ float g_GXb [NSEQ*GG];
__device__ float g_pa  [NSEQ*TT];       // pre_alpha[n][k]
__device__ float g_sv  [NSEQ*TT];       // s[n][k]
__device__ float g_hsa [(size_t)TT*NSEQ*HHN];   // h_a[k][n][h]
__device__ float g_hsb [(size_t)TT*NSEQ*HHN];   // h_b[k][n][h]
__device__ int   g_dummy;

typedef unsigned long long ull;

__device__ __forceinline__ void ffma2(ull &d, ull a, ull b) {
    asm("fma.rn.f32x2 %0, %1, %2, %0;" : "+l"(d) : "l"(a), "l"(b));
}
__device__ __forceinline__ void lds128v(unsigned a, ull &p0, ull &p1) {
    asm volatile("ld.shared.v2.b64 {%0,%1}, [%2];" : "=l"(p0), "=l"(p1) : "r"(a));
}
__device__ __forceinline__ float pairsum(ull v) {
    return __uint_as_float((unsigned)v) + __uint_as_float((unsigned)(v >> 32));
}
__device__ __forceinline__ ull dup2(float x) {
    ull v; asm("mov.b64 %0, {%1,%1};" : "=l"(v) : "f"(x)); return v;
}

// ---------------- dummy (keeps ncu capture slot on the scan) ----------------
__global__ void dummy_kernel() { if (threadIdx.x == 0) g_dummy = 1; }

// ---------------- Kernel 1: emb = x @ W_emb^T ; wemb = Wo .* emb ----------------
__global__ __launch_bounds__(256) void emb_kernel(
    const float* __restrict__ x, const float* __restrict__ Wemb,
    const float* __restrict__ Wo)
{
    __shared__ float sx[16][68];
    __shared__ float sw[16][36];
    int tid = threadIdx.x;
    int m0 = blockIdx.x * 64;
    int n0 = blockIdx.y * 32;
    int tx = tid & 15, ty = tid >> 4;
    int tm0 = tx * 4, tn0 = ty * 2;

    float acc[4][2];
#pragma unroll
    for (int q = 0; q < 4; q++) { acc[q][0] = 0.f; acc[q][1] = 0.f; }

    for (int kt = 0; kt < DD; kt += 16) {
        {
            int e = tid * 4; int m = e >> 4; int k = e & 15;
            float4 v = *(const float4*)(x + (size_t)(m0 + m) * DD + kt + k);
            sx[k][m] = v.x; sx[k+1][m] = v.y; sx[k+2][m] = v.z; sx[k+3][m] = v.w;
        }
        {
            int e = tid * 2; int n = e >> 4; int k = e & 15;
            float2 v = *(const float2*)(Wemb + (size_t)(n0 + n) * DD + kt + k);
            sw[k][n] = v.x; sw[k+1][n] = v.y;
        }
        __syncthreads();
#pragma unroll
        for (int k = 0; k < 16; k++) {
            float a0 = sx[k][tm0], a1 = sx[k][tm0+1], a2 = sx[k][tm0+2], a3 = sx[k][tm0+3];
            float b0 = sw[k][tn0], b1 = sw[k][tn0+1];
            acc[0][0] += a0*b0; acc[0][1] += a0*b1;
            acc[1][0] += a1*b0; acc[1][1] += a1*b1;
            acc[2][0] += a2*b0; acc[2][1] += a2*b1;
            acc[3][0] += a3*b0; acc[3][1] += a3*b1;
        }
        __syncthreads();
    }
#pragma unroll
    for (int q = 0; q < 4; q++)
#pragma unroll
        for (int r = 0; r < 2; r++) {
            int m = m0 + tm0 + q, n = n0 + tn0 + r;
            float v = acc[q][r];
            g_emb [m*EE + n] = v;
            g_wemb[m*EE + n] = v * Wo[n];
        }
}

// ---------------- Kernel 2: GX = emb @ Wih^T + bih (both GRUs) ----------------
__global__ __launch_bounds__(256) void gx_kernel(
    const float* __restrict__ Wih_a, const float* __restrict__ Wih_b,
    const float* __restrict__ bih_a, const float* __restrict__ bih_b)
{
    __shared__ float se [16][68];
    __shared__ float sw2[16][68];
    int tid = threadIdx.x;
    int m0 = blockIdx.x * 64;
    int n0 = blockIdx.y * 64;
    int tx = tid & 15, ty = tid >> 4;
    int tm0 = tx * 4, tn0 = ty * 4;

    const float* W; const float* bi; float* out; int nb;
    if (n0 < GG) { W = Wih_a; bi = bih_a; out = g_GXa; nb = n0; }
    else         { W = Wih_b; bi = bih_b; out = g_GXb; nb = n0 - GG; }

    float acc[4][4];
#pragma unroll
    for (int q = 0; q < 4; q++)
#pragma unroll
        for (int r = 0; r < 4; r++) acc[q][r] = 0.f;

    for (int kt = 0; kt < EE; kt += 16) {
        {
            int e = tid * 4; int m = e >> 4; int k = e & 15;
            float4 v = *(const float4*)(g_emb + (size_t)(m0 + m) * EE + kt + k);
            se[k][m] = v.x; se[k+1][m] = v.y; se[k+2][m] = v.z; se[k+3][m] = v.w;
        }
        {
            int e = tid * 4; int n = e >> 4; int k = e & 15;
            float4 v = *(const float4*)(W + (size_t)(nb + n) * EE + kt + k);
            sw2[k][n] = v.x; sw2[k+1][n] = v.y; sw2[k+2][n] = v.z; sw2[k+3][n] = v.w;
        }
        __syncthreads();
#pragma unroll
        for (int k = 0; k < 16; k++) {
            float a[4], b[4];
#pragma unroll
            for (int q = 0; q < 4; q++) a[q] = se[k][tm0+q];
#pragma unroll
            for (int r = 0; r < 4; r++) b[r] = sw2[k][tn0+r];
#pragma unroll
            for (int q = 0; q < 4; q++)
#pragma unroll
                for (int r = 0; r < 4; r++) acc[q][r] += a[q]*b[r];
        }
        __syncthreads();
    }
#pragma unroll
    for (int q = 0; q < 4; q++)
#pragma unroll
        for (int r = 0; r < 4; r++) {
            int m = m0 + tm0 + q, n = nb + tn0 + r;
            out[(size_t)m*GG + n] = acc[q][r] + bi[n];
        }
}

// ---------------- scan helpers ----------------
// P1: slice-dots for 8 seqs of one group (r,z,n gates over 32-h slice)
__device__ __forceinline__ void run_p1(
    unsigned hbase, unsigned srz_t,
    const ull* __restrict__ wn, const ull* __restrict__ wr4,
    const ull* __restrict__ wz4, float* __restrict__ pout)
{
    ull ar[8], az[8], an[8];
#pragma unroll
    for (int s = 0; s < 8; s++) { ar[s] = 0; az[s] = 0; an[s] = 0; }
#pragma unroll
    for (int blk = 0; blk < 8; blk++) {
        ull wr0, wr1, wz0, wz1, wn0, wn1;
        if (blk < 6) {
            lds128v(srz_t + blk*4096,        wr0, wr1);
            lds128v(srz_t + blk*4096 + 2048, wz0, wz1);
        } else {
            wr0 = wr4[(blk-6)*2]; wr1 = wr4[(blk-6)*2+1];
            wz0 = wz4[(blk-6)*2]; wz1 = wz4[(blk-6)*2+1];
        }
        wn0 = wn[2*blk]; wn1 = wn[2*blk+1];
#pragma unroll
        for (int s = 0; s < 8; s++) {
            ull p0, p1;
            lds128v(hbase + (unsigned)(s*528 + blk*16), p0, p1);
            ffma2(ar[s], wr0, p0); ffma2(ar[s], wr1, p1);
            ffma2(az[s], wz0, p0); ffma2(az[s], wz1, p1);
            ffma2(an[s], wn0, p0); ffma2(an[s], wn1, p1);
        }
    }
#pragma unroll
    for (int s = 0; s < 8; s++) {
        pout[(s*3 + 0)*128] = pairsum(ar[s]);
        pout[(s*3 + 1)*128] = pairsum(az[s]);
        pout[(s*3 + 2)*128] = pairsum(an[s]);
    }
}

// gi prefetch for my 2 update-seqs of a group
__device__ __forceinline__ void pf_gi(
    const float* __restrict__ GX, int b0G, int qt, int u, int j, float* gi)
{
#pragma unroll
    for (int ss = 0; ss < 2; ss++) {
        const float* p = GX + (size_t)((b0G + qt*2 + ss)*TT + j)*GG + u;
        gi[ss*3+0] = __ldg(p);
        gi[ss*3+1] = __ldg(p + 128);
        gi[ss*3+2] = __ldg(p + 256);
    }
}

// P2: GRU update of my 2 seqs for unit u
__device__ __forceinline__ void run_p2(
    const float* __restrict__ pin, float* __restrict__ sh2u,
    float* __restrict__ HS, const float* gi,
    int k, int i, int b0G, int u, int qt,
    float bhr, float bhz, float bhn)
{
#pragma unroll
    for (int ss = 0; ss < 2; ss++) {
        int s = qt*2 + ss;
        float pr = pin[(s*3+0)*128]        + pin[(s*3+0)*128 + 3072]
                 + pin[(s*3+0)*128 + 6144] + pin[(s*3+0)*128 + 9216];
        float pz = pin[(s*3+1)*128]        + pin[(s*3+1)*128 + 3072]
                 + pin[(s*3+1)*128 + 6144] + pin[(s*3+1)*128 + 9216];
        float pn = pin[(s*3+2)*128]        + pin[(s*3+2)*128 + 3072]
                 + pin[(s*3+2)*128 + 6144] + pin[(s*3+2)*128 + 9216];
        float rr = __fdividef(1.f, 1.f + __expf(-(pr + gi[ss*3+0] + bhr)));
        float zz = __fdividef(1.f, 1.f + __expf(-(pz + gi[ss*3+1] + bhz)));
        float nn = tanhf(gi[ss*3+2] + rr*(pn + bhn));
        float ho = sh2u[s*132];
        float h2 = (1.f - zz)*nn + zz*ho;
        sh2u[s*132] = h2;
        HS[((size_t)k*NSEQ + (b0G + s)*TT + i)*HHN + u] = h2;
    }
}

// ---------------- Kernel 3: persistent GRU scan, 2-group pipelined ----------------
// 512 threads = (unit u 0..127) x (h-quarter 0..3). Task = position i; group A =
// batches 0-7, group B = batches 8-15. P2(G) overlapped with P1(other G).
__global__ __launch_bounds__(512, 1) void scan_kernel(
    const float* __restrict__ Whh_a, const float* __restrict__ Whh_b,
    const float* __restrict__ bhh_a, const float* __restrict__ bhh_b,
    int RA, int Rtot)
{
    extern __shared__ float smem[];
    float* sh2 = smem + OFF_SH2;

    unsigned sbase;
    asm("{ .reg .u64 t; cvta.to.shared.u64 t, %1; cvt.u32.u64 %0, t; }"
        : "=r"(sbase) : "l"(smem));
    unsigned shA = sbase + OFF_SH2 * 4;

    int tid = threadIdx.x;
    int u = tid & 127, qt = tid >> 7;
    bool roleA = (blockIdx.x < RA);
    int rc = roleA ? blockIdx.x : blockIdx.x - RA;
    int R  = roleA ? RA : (Rtot - RA);

    const float* Whh = roleA ? Whh_a : Whh_b;
    const float* bhh = roleA ? bhh_a : bhh_b;
    const float* GX  = roleA ? g_GXa : g_GXb;
    float* HS        = roleA ? g_hsa : g_hsb;

    // stage r,z weight pairs (12 of 16 per qt) to SMEM, ull2-interleaved:
    // entry e = ((qt*6+blk)*2+g2)*128 + u holds pairs (p, p+1), p = qt*16+2*blk
    {
        const ull* W2 = (const ull*)Whh;
        ull* sz = (ull*)smem;
        for (int e = tid; e < 6144; e += 512) {
            int uu = e & 127;
            int t  = e >> 7;
            int g2 = t & 1;
            int qb = t >> 1;
            int qq = qb / 6, bb2 = qb - qq*6;
            int p  = qq*16 + 2*bb2;
            int row = g2*128 + uu;
            sz[2*e]   = W2[(size_t)row*64 + p];
            sz[2*e+1] = W2[(size_t)row*64 + p + 1];
        }
    }
    // register weights: n-gate slice (16 pairs) + last 4 r,z pairs
    ull wn[16], wr4[4], wz4[4];
    {
        const ull* W2 = (const ull*)Whh;
#pragma unroll
        for (int q = 0; q < 16; q++) wn[q] = W2[(size_t)(256 + u)*64 + qt*16 + q];
#pragma unroll
        for (int q = 0; q < 4; q++) {
            wr4[q] = W2[(size_t)u*64         + qt*16 + 12 + q];
            wz4[q] = W2[(size_t)(128 + u)*64 + qt*16 + 12 + q];
        }
    }
    float bhr = bhh[u], bhz = bhh[128 + u], bhn = bhh[256 + u];

    unsigned srz_t  = sbase + (unsigned)qt*24576 + (unsigned)u*16;
    unsigned hbaseA = shA + (unsigned)qt*128;
    unsigned hbaseB = hbaseA + 8*528;
    float* pA_out = smem + OFF_PA + qt*3072 + u;
    float* pB_out = smem + OFF_PB + qt*3072 + u;
    const float* pA_in = smem + OFF_PA + u;
    const float* pB_in = smem + OFF_PB + u;
    float* sh2uA = sh2 + u;
    float* sh2uB = sh2 + 8*132 + u;
    __syncthreads();

    for (int mIdx = 0;; mIdx++) {
        int t = mIdx*R + ((mIdx & 1) ? (R - 1 - rc) : rc);   // snake
        if (t >= NTASK) break;
        int i = 127 - t;                                      // longest-first

        __syncthreads();
        for (int idx = tid; idx < 16*132; idx += 512) sh2[idx] = 0.f;
        __syncthreads();

        float giA[6], giB[6];
        pf_gi(GX, 0, qt, u, i, giA);
        run_p1(hbaseA, srz_t, wn, wr4, wz4, pA_out);

        for (int k = 0; k <= i; k++) {
            pf_gi(GX, 8, qt, u, i - k, giB);
            __syncthreads();
            run_p2(pA_in, sh2uA, HS, giA, k, i, 0, u, qt, bhr, bhz, bhn);
            if (k < i) pf_gi(GX, 0, qt, u, i - k - 1, giA);
            run_p1(hbaseB, srz_t, wn, wr4, wz4, pB_out);
            __syncthreads();
            run_p2(pB_in, sh2uB, HS, giB, k, i, 8, u, qt, bhr, bhz, bhn);
            if (k < i) run_p1(hbaseA, srz_t, wn, wr4, wz4, pA_out);
        }
    }
}

// ---------------- Kernel 4: pre_alpha = 0.5*Wa·h_a + ba ----------------
__global__ __launch_bounds__(256) void alpha_kernel(
    const float* __restrict__ Wa, const float* __restrict__ ba)
{
    int r = blockIdx.x * 8 + (threadIdx.x >> 5);   // (k,n) flat
    int lane = threadIdx.x & 31;
    int k = r >> 11, n = r & 2047, i = n & 127;
    if (k > i) return;
    const float4 hv = *(const float4*)(g_hsa + ((size_t)k*NSEQ + n)*HHN + lane*4);
    const float4 wv = *(const float4*)(Wa + lane*4);
    float p = 0.5f*(hv.x*wv.x + hv.y*wv.y + hv.z*wv.z + hv.w*wv.w);
#pragma unroll
    for (int o = 16; o > 0; o >>= 1)
        p += __shfl_xor_sync(0xffffffffu, p, o);
    if (lane == 0) g_pa[(size_t)n*TT + k] = p + ba[0];
}

// ---------------- Kernel 5: beta GEMM + wemb dot -> s[n][k] (f32x2) ----------------
__global__ __launch_bounds__(256) void beta_kernel(
    const float* __restrict__ Wb, const float* __restrict__ bb)
{
    int k  = blockIdx.x;          // 0..127
    int nb = blockIdx.y;          // 0..31
    int i0 = (nb & 1) * 64;
    if (i0 + 63 < k) return;
    int n0 = nb * 64;
    int b  = n0 >> 7;

    __shared__ float shh[16][68];
    __shared__ float sww[16][132];
    __shared__ float red[64][17];

    int tid = threadIdx.x;
    int tx = tid & 15, ty = tid >> 4;
    int r0 = tx * 4, e0 = ty * 8;

    const float* hb = g_hsb + ((size_t)k*NSEQ + n0)*HHN;

    ull acc2[4][4];
#pragma unroll
    for (int q = 0; q < 4; q++)
#pragma unroll
        for (int e = 0; e < 4; e++) acc2[q][e] = 0;

    for (int kt = 0; kt < HHN; kt += 16) {
        {
            int e = tid * 4; int rr = e >> 4; int h = e & 15;
            float4 v = *(const float4*)(hb + (size_t)rr*HHN + kt + h);
            shh[h][rr] = v.x; shh[h+1][rr] = v.y; shh[h+2][rr] = v.z; shh[h+3][rr] = v.w;
        }
        {
            int e2 = tid * 8; int ee = e2 >> 4; int h = e2 & 15;
            float4 v0 = *(const float4*)(Wb + (size_t)ee*HHN + kt + h);
            float4 v1 = *(const float4*)(Wb + (size_t)ee*HHN + kt + h + 4);
            sww[h  ][ee] = 0.5f*v0.x; sww[h+1][ee] = 0.5f*v0.y;
            sww[h+2][ee] = 0.5f*v0.z; sww[h+3][ee] = 0.5f*v0.w;
            sww[h+4][ee] = 0.5f*v1.x; sww[h+5][ee] = 0.5f*v1.y;
            sww[h+6][ee] = 0.5f*v1.z; sww[h+7][ee] = 0.5f*v1.w;
        }
        __syncthreads();
#pragma unroll
        for (int kk = 0; kk < 16; kk++) {
            ull av[4], bv[4];
#pragma unroll
            for (int q = 0; q < 4; q++) av[q] = dup2(shh[kk][r0+q]);
            const ull* bp = (const ull*)&sww[kk][e0];
#pragma unroll
            for (int e = 0; e < 4; e++) bv[e] = bp[e];
#pragma unroll
            for (int q = 0; q < 4; q++)
#pragma unroll
                for (int e = 0; e < 4; e++) ffma2(acc2[q][e], av[q], bv[e]);
        }
        __syncthreads();
    }

    float bbv[8];
#pragma unroll
    for (int e = 0; e < 8; e++) bbv[e] = bb[e0 + e];

#pragma unroll
    for (int q = 0; q < 4; q++) {
        int n = n0 + r0 + q;
        int i = n & 127;
        int j = i - k;
        const float* wm = g_wemb + ((size_t)b*TT + (j >= 0 ? j : 0))*EE + e0;
        float p = 0.f;
#pragma unroll
        for (int e = 0; e < 4; e++) {
            float lo = __uint_as_float((unsigned)acc2[q][e]);
            float hi = __uint_as_float((unsigned)(acc2[q][e] >> 32));
            p += tanhf(lo + bbv[2*e])   * wm[2*e];
            p += tanhf(hi + bbv[2*e+1]) * wm[2*e+1];
        }
        red[r0 + q][ty] = p;
    }
    __syncthreads();
    if (tid < 64) {
        float v = 0.f;
#pragma unroll
        for (int t = 0; t < 16; t++) v += red[tid][t];
        int n = n0 + tid;
        int i = n & 127;
        if (k <= i) g_sv[(size_t)n*TT + k] = v;
    }
}

// ---------------- Kernel 6: masked softmax combine ----------------
__global__ __launch_bounds__(256) void combine_kernel(
    const float* __restrict__ bo, float* __restrict__ out)
{
    int w = blockIdx.x * 8 + (threadIdx.x >> 5);
    int lane = threadIdx.x & 31;
    if (w >= NSEQ) return;
    int i = w & 127;
    float num = 0.f, den = 0.f;
    for (int k = lane; k <= i; k += 32) {
        float ev = __expf(g_pa[(size_t)w*TT + k]);
        num += ev * g_sv[(size_t)w*TT + k];
        den += ev;
    }
#pragma unroll
    for (int o = 16; o > 0; o >>= 1) {
        num += __shfl_xor_sync(0xffffffffu, num, o);
        den += __shfl_xor_sync(0xffffffffu, den, o);
    }
    if (lane == 0) out[w] = num / den + bo[0];
}

// ---------------- launch ----------------
extern "C" void kernel_launch(void* const* d_in, const int* in_sizes, int n_in,
                              void* d_out, int out_size)
{
    const float* x     = (const float*)d_in[0];
    const float* Wemb  = (const float*)d_in[1];
    const float* Wih_a = (const float*)d_in[2];
    const float* Whh_a = (const float*)d_in[3];
    const float* bih_a = (const float*)d_in[4];
    const float* bhh_a = (const float*)d_in[5];
    const float* Wa    = (const float*)d_in[6];
    const float* ba    = (const float*)d_in[7];
    const float* Wih_b = (const float*)d_in[8];
    const float* Whh_b = (const float*)d_in[9];
    const float* bih_b = (const float*)d_in[10];
    const float* bhh_b = (const float*)d_in[11];
    const float* Wb    = (const float*)d_in[12];
    const float* bb    = (const float*)d_in[13];
    const float* Wo    = (const float*)d_in[14];
    const float* bo    = (const float*)d_in[15];
    float* out = (float*)d_out;

    int dev = 0;
    cudaGetDevice(&dev);
    int sms = 148;
    cudaDeviceGetAttribute(&sms, cudaDevAttrMultiProcessorCount, dev);
    int RA = sms / 2;

    size_t smem_bytes = (size_t)SMEM_FLOATS * sizeof(float);
    cudaFuncSetAttribute(scan_kernel,
                         cudaFuncAttributeMaxDynamicSharedMemorySize,
                         (int)smem_bytes);

    dummy_kernel<<<1, 32>>>();
    emb_kernel<<<dim3(32, 4), 256>>>(x, Wemb, Wo);
    gx_kernel<<<dim3(32, 12), 256>>>(Wih_a, Wih_b, bih_a, bih_b);
    scan_kernel<<<sms, 512, smem_bytes>>>(Whh_a, Whh_b, bhh_a, bhh_b, RA, sms);
    alpha_kernel<<<(NSEQ*TT)/8, 256>>>(Wa, ba);
    beta_kernel<<<dim3(TT, NSEQ/64), 256>>>(Wb, bb);
    combine_kernel<<<NSEQ/8, 256>>>(bo, out);
}

// round 9
// speedup vs baseline: 1.0696x; 1.0696x over previous
#include <cuda_runtime.h>

#define BB 16
#define TT 128
#define DD 1024
#define EE 128
#define HHN 128
#define GG 384           // 3*H
#define NSEQ (BB*TT)     // 2048
#define NG8  256         // groups of 8 seqs (2 per time position i)

// scan smem layout (floats)
// [0, 32768): r,z weight pairs, ull2 entries: idx=(g*16+blk)*256+u2  (128KB)
#define OFF_H   32768                   // 2 x 8 x 132 hidden-state buffers
#define SMEM_FLOATS (OFF_H + 2*8*132)   // 34880 floats = 139520 B

// ---------------- scratch (device globals; no allocation) ----------------
__device__ float g_emb [NSEQ*EE];
__device__ float g_wemb[NSEQ*EE];       // Wo[e]*emb
__device__ float g_GXa [NSEQ*GG];
__device__ float g_GXb [NSEQ*GG];
__device__ float g_pa  [NSEQ*TT];       // pre_alpha[n][k]
__device__ float g_sv  [NSEQ*TT];       // s[n][k]
__device__ float g_hsa [(size_t)TT*NSEQ*HHN];   // h_a[k][n][h]
__device__ float g_hsb [(size_t)TT*NSEQ*HHN];   // h_b[k][n][h]
__device__ int   g_dummy;

typedef unsigned long long ull;

__device__ __forceinline__ void ffma2(ull &d, ull a, ull b) {
    asm("fma.rn.f32x2 %0, %1, %2, %0;" : "+l"(d) : "l"(a), "l"(b));
}
__device__ __forceinline__ void lds128v(unsigned a, ull &p0, ull &p1) {
    asm volatile("ld.shared.v2.b64 {%0,%1}, [%2];" : "=l"(p0), "=l"(p1) : "r"(a));
}
__device__ __forceinline__ float pairsum(ull v) {
    return __uint_as_float((unsigned)v) + __uint_as_float((unsigned)(v >> 32));
}
__device__ __forceinline__ ull dup2(float x) {
    ull v; asm("mov.b64 %0, {%1,%1};" : "=l"(v) : "f"(x)); return v;
}
__device__ __forceinline__ float tanhhw(float x) {
    float y; asm("tanh.approx.f32 %0, %1;" : "=f"(y) : "f"(x)); return y;
}

// ---------------- dummy (keeps ncu capture slot on the scan) ----------------
__global__ void dummy_kernel() { if (threadIdx.x == 0) g_dummy = 1; }

// ---------------- Kernel 1: emb = x @ W_emb^T ; wemb = Wo .* emb ----------------
__global__ __launch_bounds__(256) void emb_kernel(
    const float* __restrict__ x, const float* __restrict__ Wemb,
    const float* __restrict__ Wo)
{
    __shared__ float sx[16][68];
    __shared__ float sw[16][36];
    int tid = threadIdx.x;
    int m0 = blockIdx.x * 64;
    int n0 = blockIdx.y * 32;
    int tx = tid & 15, ty = tid >> 4;
    int tm0 = tx * 4, tn0 = ty * 2;

    float acc[4][2];
#pragma unroll
    for (int q = 0; q < 4; q++) { acc[q][0] = 0.f; acc[q][1] = 0.f; }

    for (int kt = 0; kt < DD; kt += 16) {
        {
            int e = tid * 4; int m = e >> 4; int k = e & 15;
            float4 v = *(const float4*)(x + (size_t)(m0 + m) * DD + kt + k);
            sx[k][m] = v.x; sx[k+1][m] = v.y; sx[k+2][m] = v.z; sx[k+3][m] = v.w;
        }
        {
            int e = tid * 2; int n = e >> 4; int k = e & 15;
            float2 v = *(const float2*)(Wemb + (size_t)(n0 + n) * DD + kt + k);
            sw[k][n] = v.x; sw[k+1][n] = v.y;
        }
        __syncthreads();
#pragma unroll
        for (int k = 0; k < 16; k++) {
            float a0 = sx[k][tm0], a1 = sx[k][tm0+1], a2 = sx[k][tm0+2], a3 = sx[k][tm0+3];
            float b0 = sw[k][tn0], b1 = sw[k][tn0+1];
            acc[0][0] += a0*b0; acc[0][1] += a0*b1;
            acc[1][0] += a1*b0; acc[1][1] += a1*b1;
            acc[2][0] += a2*b0; acc[2][1] += a2*b1;
            acc[3][0] += a3*b0; acc[3][1] += a3*b1;
        }
        __syncthreads();
    }
#pragma unroll
    for (int q = 0; q < 4; q++)
#pragma unroll
        for (int r = 0; r < 2; r++) {
            int m = m0 + tm0 + q, n = n0 + tn0 + r;
            float v = acc[q][r];
            g_emb [m*EE + n] = v;
            g_wemb[m*EE + n] = v * Wo[n];
        }
}

// ---------------- Kernel 2: GX = emb @ Wih^T + bih (both GRUs) ----------------
__global__ __launch_bounds__(256) void gx_kernel(
    const float* __restrict__ Wih_a, const float* __restrict__ Wih_b,
    const float* __restrict__ bih_a, const float* __restrict__ bih_b)
{
    __shared__ float se [16][68];
    __shared__ float sw2[16][68];
    int tid = threadIdx.x;
    int m0 = blockIdx.x * 64;
    int n0 = blockIdx.y * 64;
    int tx = tid & 15, ty = tid >> 4;
    int tm0 = tx * 4, tn0 = ty * 4;

    const float* W; const float* bi; float* out; int nb;
    if (n0 < GG) { W = Wih_a; bi = bih_a; out = g_GXa; nb = n0; }
    else         { W = Wih_b; bi = bih_b; out = g_GXb; nb = n0 - GG; }

    float acc[4][4];
#pragma unroll
    for (int q = 0; q < 4; q++)
#pragma unroll
        for (int r = 0; r < 4; r++) acc[q][r] = 0.f;

    for (int kt = 0; kt < EE; kt += 16) {
        {
            int e = tid * 4; int m = e >> 4; int k = e & 15;
            float4 v = *(const float4*)(g_emb + (size_t)(m0 + m) * EE + kt + k);
            se[k][m] = v.x; se[k+1][m] = v.y; se[k+2][m] = v.z; se[k+3][m] = v.w;
        }
        {
            int e = tid * 4; int n = e >> 4; int k = e & 15;
            float4 v = *(const float4*)(W + (size_t)(nb + n) * EE + kt + k);
            sw2[k][n] = v.x; sw2[k+1][n] = v.y; sw2[k+2][n] = v.z; sw2[k+3][n] = v.w;
        }
        __syncthreads();
#pragma unroll
        for (int k = 0; k < 16; k++) {
            float a[4], b[4];
#pragma unroll
            for (int q = 0; q < 4; q++) a[q] = se[k][tm0+q];
#pragma unroll
            for (int r = 0; r < 4; r++) b[r] = sw2[k][tn0+r];
#pragma unroll
            for (int q = 0; q < 4; q++)
#pragma unroll
                for (int r = 0; r < 4; r++) acc[q][r] += a[q]*b[r];
        }
        __syncthreads();
    }
#pragma unroll
    for (int q = 0; q < 4; q++)
#pragma unroll
        for (int r = 0; r < 4; r++) {
            int m = m0 + tm0 + q, n = nb + tn0 + r;
            out[(size_t)m*GG + n] = acc[q][r] + bi[n];
        }
}

// ---------------- Kernel 3: persistent GRU scan (pair-per-unit, 1 BAR/step) ----
// 256 threads: warp w covers units u = w*16 + (lane>>1); parity = lane&1 picks
// the h-half. Thread computes r,z,n rows of its unit over its half for 8 seqs;
// partial exchange via SHFL.XOR(1); thread updates 4 seqs of its unit.
__global__ __launch_bounds__(256, 1) void scan_kernel(
    const float* __restrict__ Whh_a, const float* __restrict__ Whh_b,
    const float* __restrict__ bhh_a, const float* __restrict__ bhh_b,
    int RA, int Rtot)
{
    extern __shared__ float smem[];
    float* shv = smem + OFF_H;

    unsigned sbase;
    asm("{ .reg .u64 t; cvta.to.shared.u64 t, %1; cvt.u32.u64 %0, t; }"
        : "=r"(sbase) : "l"(smem));
    unsigned shH = sbase + OFF_H * 4;      // h buffers: 2 x (8 x 132 floats)

    int tid = threadIdx.x;
    int lane = tid & 31, w = tid >> 5;
    int u = w*16 + (lane >> 1);
    int parity = lane & 1;
    bool roleA = (blockIdx.x < RA);
    int rc = roleA ? blockIdx.x : blockIdx.x - RA;
    int R  = roleA ? RA : (Rtot - RA);

    const float* Whh = roleA ? Whh_a : Whh_b;
    const float* bhh = roleA ? bhh_a : bhh_b;
    const float* GX  = roleA ? g_GXa : g_GXb;
    float* HS        = roleA ? g_hsa : g_hsb;

    // stage r,z weight pairs into SMEM as ull2 entries: idx=(g*16+blk)*256+u2,
    // entry holds pairs (2*blk, 2*blk+1) of row g*128+(u2>>1) over half (u2&1).
    {
        const ull* W2 = (const ull*)Whh;
        ull* sz = (ull*)smem;
        for (int e = tid; e < 8192; e += 256) {
            int u2  = e & 255;
            int blk = (e >> 8) & 15;
            int g   = e >> 12;
            int uu = u2 >> 1, par = u2 & 1;
            const ull* src = W2 + (size_t)(g*128 + uu)*64 + par*32 + 2*blk;
            sz[2*e]   = src[0];
            sz[2*e+1] = src[1];
        }
    }
    // n-gate half-row in registers (32 pairs)
    ull wn[32];
    {
        const ull* W2 = (const ull*)Whh;
#pragma unroll
        for (int q = 0; q < 32; q++)
            wn[q] = W2[(size_t)(256 + u)*64 + parity*32 + q];
    }
    float bhr = bhh[u], bhz = bhh[128 + u], bhn = bhh[256 + u];

    int u2w = w*32 + lane;                           // = u*2+parity
    unsigned rz_r = sbase + (unsigned)u2w * 16;      // + blk*4096
    unsigned rz_z = rz_r + 65536;
    unsigned hoff = parity ? 68u*4u : 0u;            // my half within a row
    int upos = (u < 64) ? u : (68 + (u - 64));       // write position of unit u
    int sqb = parity * 4;                            // my 4 seqs: sqb..sqb+3
    __syncthreads();

    for (int mIdx = 0;; mIdx++) {
        int g = mIdx*R + ((mIdx & 1) ? (R - 1 - rc) : rc);   // snake
        if (g >= NG8) break;

        int i  = 127 - (g >> 1);      // longest-first
        int b0 = (g & 1) * 8;

        __syncthreads();              // protect prev group's readers
        for (int idx = tid; idx < 8*132; idx += 256) shv[idx] = 0.f;  // buf0
        __syncthreads();

        float hold[4];
#pragma unroll
        for (int ss = 0; ss < 4; ss++) hold[ss] = 0.f;

        for (int k = 0; k <= i; k++) {
            int j = i - k;
            // prefetch gi for my 4 seqs (L2-resident; covered by P1)
            float gir[4], giz[4], gin[4];
#pragma unroll
            for (int ss = 0; ss < 4; ss++) {
                const float* p = GX + (size_t)((b0 + sqb + ss)*TT + j)*GG + u;
                gir[ss] = __ldg(p);
                giz[ss] = __ldg(p + 128);
                gin[ss] = __ldg(p + 256);
            }

            // ---- P1: half-dots, 3 gates x 8 seqs (reads buf k&1) ----
            unsigned hb = shH + (unsigned)((k & 1) * 8*132) * 4 + hoff;
            ull ar[8], az[8], an[8];
#pragma unroll
            for (int s = 0; s < 8; s++) { ar[s] = 0; az[s] = 0; an[s] = 0; }
#pragma unroll
            for (int blk = 0; blk < 16; blk++) {
                ull wr0, wr1, wz0, wz1;
                lds128v(rz_r + (unsigned)blk*4096, wr0, wr1);
                lds128v(rz_z + (unsigned)blk*4096, wz0, wz1);
                ull wn0 = wn[2*blk], wn1 = wn[2*blk+1];
#pragma unroll
                for (int s = 0; s < 8; s++) {
                    ull p0, p1;
                    lds128v(hb + (unsigned)(s*528 + blk*16), p0, p1);
                    ffma2(ar[s], wr0, p0); ffma2(ar[s], wr1, p1);
                    ffma2(az[s], wz0, p0); ffma2(az[s], wz1, p1);
                    ffma2(an[s], wn0, p0); ffma2(an[s], wn1, p1);
                }
            }

            // ---- exchange partials with pair lane (12 SHFL) ----
            float fr[4], fz[4], fn[4];
            int ob = parity ? 0 : 4;   // provide the partner's seqs
#pragma unroll
            for (int ss = 0; ss < 4; ss++) {
                float pr = pairsum(ar[ob + ss]);
                float pz = pairsum(az[ob + ss]);
                float pn = pairsum(an[ob + ss]);
                float rr_ = __shfl_xor_sync(0xffffffffu, pr, 1);
                float rz_ = __shfl_xor_sync(0xffffffffu, pz, 1);
                float rn_ = __shfl_xor_sync(0xffffffffu, pn, 1);
                fr[ss] = pairsum(ar[sqb + ss]) + rr_;
                fz[ss] = pairsum(az[sqb + ss]) + rz_;
                fn[ss] = pairsum(an[sqb + ss]) + rn_;
            }

            // ---- P2: GRU update of my 4 seqs (writes buf (k+1)&1) ----
            int bufn = ((k + 1) & 1) * 8 * 132;
#pragma unroll
            for (int ss = 0; ss < 4; ss++) {
                int s = sqb + ss;
                float rr = 0.5f + 0.5f * tanhhw(0.5f*(fr[ss] + gir[ss] + bhr));
                float zz = 0.5f + 0.5f * tanhhw(0.5f*(fz[ss] + giz[ss] + bhz));
                float nn = tanhhw(gin[ss] + rr*(fn[ss] + bhn));
                float h2 = (1.f - zz)*nn + zz*hold[ss];
                hold[ss] = h2;
                shv[bufn + s*132 + upos] = h2;
                HS[((size_t)k*NSEQ + (b0 + s)*TT + i)*HHN + u] = h2;
            }
            __syncthreads();
        } // k
    } // groups
}

// ---------------- Kernel 4: pre_alpha = 0.5*Wa·h_a + ba ----------------
__global__ __launch_bounds__(256) void alpha_kernel(
    const float* __restrict__ Wa, const float* __restrict__ ba)
{
    int r = blockIdx.x * 8 + (threadIdx.x >> 5);   // (k,n) flat
    int lane = threadIdx.x & 31;
    int k = r >> 11, n = r & 2047, i = n & 127;
    if (k > i) return;
    const float4 hv = *(const float4*)(g_hsa + ((size_t)k*NSEQ + n)*HHN + lane*4);
    const float4 wv = *(const float4*)(Wa + lane*4);
    float p = 0.5f*(hv.x*wv.x + hv.y*wv.y + hv.z*wv.z + hv.w*wv.w);
#pragma unroll
    for (int o = 16; o > 0; o >>= 1)
        p += __shfl_xor_sync(0xffffffffu, p, o);
    if (lane == 0) g_pa[(size_t)n*TT + k] = p + ba[0];
}

// ---------------- Kernel 5: beta GEMM + wemb dot -> s[n][k] (f32x2) ----------------
__global__ __launch_bounds__(256) void beta_kernel(
    const float* __restrict__ Wb, const float* __restrict__ bb)
{
    int k  = blockIdx.x;          // 0..127
    int nb = blockIdx.y;          // 0..31
    int i0 = (nb & 1) * 64;
    if (i0 + 63 < k) return;
    int n0 = nb * 64;
    int b  = n0 >> 7;

    __shared__ float shh[16][68];
    __shared__ float sww[16][132];
    __shared__ float red[64][17];

    int tid = threadIdx.x;
    int tx = tid & 15, ty = tid >> 4;
    int r0 = tx * 4, e0 = ty * 8;

    const float* hb = g_hsb + ((size_t)k*NSEQ + n0)*HHN;

    ull acc2[4][4];
#pragma unroll
    for (int q = 0; q < 4; q++)
#pragma unroll
        for (int e = 0; e < 4; e++) acc2[q][e] = 0;

    for (int kt = 0; kt < HHN; kt += 16) {
        {
            int e = tid * 4; int rr = e >> 4; int h = e & 15;
            float4 v = *(const float4*)(hb + (size_t)rr*HHN + kt + h);
            shh[h][rr] = v.x; shh[h+1][rr] = v.y; shh[h+2][rr] = v.z; shh[h+3][rr] = v.w;
        }
        {
            int e2 = tid * 8; int ee = e2 >> 4; int h = e2 & 15;
            float4 v0 = *(const float4*)(Wb + (size_t)ee*HHN + kt + h);
            float4 v1 = *(const float4*)(Wb + (size_t)ee*HHN + kt + h + 4);
            sww[h  ][ee] = 0.5f*v0.x; sww[h+1][ee] = 0.5f*v0.y;
            sww[h+2][ee] = 0.5f*v0.z; sww[h+3][ee] = 0.5f*v0.w;
            sww[h+4][ee] = 0.5f*v1.x; sww[h+5][ee] = 0.5f*v1.y;
            sww[h+6][ee] = 0.5f*v1.z; sww[h+7][ee] = 0.5f*v1.w;
        }
        __syncthreads();
#pragma unroll
        for (int kk = 0; kk < 16; kk++) {
            ull av[4], bv[4];
#pragma unroll
            for (int q = 0; q < 4; q++) av[q] = dup2(shh[kk][r0+q]);
            const ull* bp = (const ull*)&sww[kk][e0];
#pragma unroll
            for (int e = 0; e < 4; e++) bv[e] = bp[e];
#pragma unroll
            for (int q = 0; q < 4; q++)
#pragma unroll
                for (int e = 0; e < 4; e++) ffma2(acc2[q][e], av[q], bv[e]);
        }
        __syncthreads();
    }

    float bbv[8];
#pragma unroll
    for (int e = 0; e < 8; e++) bbv[e] = bb[e0 + e];

#pragma unroll
    for (int q = 0; q < 4; q++) {
        int n = n0 + r0 + q;
        int i = n & 127;
        int j = i - k;
        const float* wm = g_wemb + ((size_t)b*TT + (j >= 0 ? j : 0))*EE + e0;
        float p = 0.f;
#pragma unroll
        for (int e = 0; e < 4; e++) {
            float lo = __uint_as_float((unsigned)acc2[q][e]);
            float hi = __uint_as_float((unsigned)(acc2[q][e] >> 32));
            p += tanhf(lo + bbv[2*e])   * wm[2*e];
            p += tanhf(hi + bbv[2*e+1]) * wm[2*e+1];
        }
        red[r0 + q][ty] = p;
    }
    __syncthreads();
    if (tid < 64) {
        float v = 0.f;
#pragma unroll
        for (int t = 0; t < 16; t++) v += red[tid][t];
        int n = n0 + tid;
        int i = n & 127;
        if (k <= i) g_sv[(size_t)n*TT + k] = v;
    }
}

// ---------------- Kernel 6: masked softmax combine ----------------
__global__ __launch_bounds__(256) void combine_kernel(
    const float* __restrict__ bo, float* __restrict__ out)
{
    int w = blockIdx.x * 8 + (threadIdx.x >> 5);
    int lane = threadIdx.x & 31;
    if (w >= NSEQ) return;
    int i = w & 127;
    float num = 0.f, den = 0.f;
    for (int k = lane; k <= i; k += 32) {
        float ev = __expf(g_pa[(size_t)w*TT + k]);
        num += ev * g_sv[(size_t)w*TT + k];
        den += ev;
    }
#pragma unroll
    for (int o = 16; o > 0; o >>= 1) {
        num += __shfl_xor_sync(0xffffffffu, num, o);
        den += __shfl_xor_sync(0xffffffffu, den, o);
    }
    if (lane == 0) out[w] = num / den + bo[0];
}

// ---------------- launch ----------------
extern "C" void kernel_launch(void* const* d_in, const int* in_sizes, int n_in,
                              void* d_out, int out_size)
{
    const float* x     = (const float*)d_in[0];
    const float* Wemb  = (const float*)d_in[1];
    const float* Wih_a = (const float*)d_in[2];
    const float* Whh_a = (const float*)d_in[3];
    const float* bih_a = (const float*)d_in[4];
    const float* bhh_a = (const float*)d_in[5];
    const float* Wa    = (const float*)d_in[6];
    const float* ba    = (const float*)d_in[7];
    const float* Wih_b = (const float*)d_in[8];
    const float* Whh_b = (const float*)d_in[9];
    const float* bih_b = (const float*)d_in[10];
    const float* bhh_b = (const float*)d_in[11];
    const float* Wb    = (const float*)d_in[12];
    const float* bb    = (const float*)d_in[13];
    const float* Wo    = (const float*)d_in[14];
    const float* bo    = (const float*)d_in[15];
    float* out = (float*)d_out;

    int dev = 0;
    cudaGetDevice(&dev);
    int sms = 148;
    cudaDeviceGetAttribute(&sms, cudaDevAttrMultiProcessorCount, dev);
    int RA = sms / 2;

    size_t smem_bytes = (size_t)SMEM_FLOATS * sizeof(float);
    cudaFuncSetAttribute(scan_kernel,
                         cudaFuncAttributeMaxDynamicSharedMemorySize,
                         (int)smem_bytes);

    dummy_kernel<<<1, 32>>>();
    emb_kernel<<<dim3(32, 4), 256>>>(x, Wemb, Wo);
    gx_kernel<<<dim3(32, 12), 256>>>(Wih_a, Wih_b, bih_a, bih_b);
    scan_kernel<<<sms, 256, smem_bytes>>>(Whh_a, Whh_b, bhh_a, bhh_b, RA, sms);
    alpha_kernel<<<(NSEQ*TT)/8, 256>>>(Wa, ba);
    beta_kernel<<<dim3(TT, NSEQ/64), 256>>>(Wb, bb);
    combine_kernel<<<NSEQ/8, 256>>>(bo, out);
}

// round 10
// speedup vs baseline: 1.2537x; 1.1722x over previous
#include <cuda_runtime.h>

#define BB 16
#define TT 128
#define DD 1024
#define EE 128
#define HHN 128
#define GG 384           // 3*H
#define NSEQ (BB*TT)     // 2048
#define NG8  256         // groups of 8 seqs (2 per time position i)

// scan smem layout (floats)
// [0, 49152): weight ull2 entries: e = (g*32+pp)*128 + u  -> pairs (2pp,2pp+1)
//             of Whh row (g*128+u).  196608 bytes.
#define OFF_H   49152                   // 2 x 8 x 132 hidden-state buffers
#define SMEM_FLOATS (OFF_H + 2*8*132)   // 51264 floats = 205056 B

// ---------------- scratch (device globals; no allocation) ----------------
__device__ float g_emb [NSEQ*EE];
__device__ float g_wemb[NSEQ*EE];       // Wo[e]*emb
__device__ float g_GXa [NSEQ*GG];
__device__ float g_GXb [NSEQ*GG];
__device__ float g_pa  [NSEQ*TT];       // pre_alpha[n][k]
__device__ float g_sv  [NSEQ*TT];       // s[n][k]
__device__ float g_hsa [(size_t)TT*NSEQ*HHN];   // h_a[k][n][h]
__device__ float g_hsb [(size_t)TT*NSEQ*HHN];   // h_b[k][n][h]
__device__ int   g_dummy;

typedef unsigned long long ull;

__device__ __forceinline__ void ffma2(ull &d, ull a, ull b) {
    asm("fma.rn.f32x2 %0, %1, %2, %0;" : "+l"(d) : "l"(a), "l"(b));
}
__device__ __forceinline__ void lds128v(unsigned a, ull &p0, ull &p1) {
    asm volatile("ld.shared.v2.b64 {%0,%1}, [%2];" : "=l"(p0), "=l"(p1) : "r"(a));
}
__device__ __forceinline__ float pairsum(ull v) {
    return __uint_as_float((unsigned)v) + __uint_as_float((unsigned)(v >> 32));
}
__device__ __forceinline__ ull dup2(float x) {
    ull v; asm("mov.b64 %0, {%1,%1};" : "=l"(v) : "f"(x)); return v;
}
__device__ __forceinline__ float tanhhw(float x) {
    float y; asm("tanh.approx.f32 %0, %1;" : "=f"(y) : "f"(x)); return y;
}

// ---------------- dummy (keeps ncu capture slot on the scan) ----------------
__global__ void dummy_kernel() { if (threadIdx.x == 0) g_dummy = 1; }

// ---------------- Kernel 1: emb = x @ W_emb^T ; wemb = Wo .* emb ----------------
__global__ __launch_bounds__(256) void emb_kernel(
    const float* __restrict__ x, const float* __restrict__ Wemb,
    const float* __restrict__ Wo)
{
    __shared__ float sx[16][68];
    __shared__ float sw[16][36];
    int tid = threadIdx.x;
    int m0 = blockIdx.x * 64;
    int n0 = blockIdx.y * 32;
    int tx = tid & 15, ty = tid >> 4;
    int tm0 = tx * 4, tn0 = ty * 2;

    float acc[4][2];
#pragma unroll
    for (int q = 0; q < 4; q++) { acc[q][0] = 0.f; acc[q][1] = 0.f; }

    for (int kt = 0; kt < DD; kt += 16) {
        {
            int e = tid * 4; int m = e >> 4; int k = e & 15;
            float4 v = *(const float4*)(x + (size_t)(m0 + m) * DD + kt + k);
            sx[k][m] = v.x; sx[k+1][m] = v.y; sx[k+2][m] = v.z; sx[k+3][m] = v.w;
        }
        {
            int e = tid * 2; int n = e >> 4; int k = e & 15;
            float2 v = *(const float2*)(Wemb + (size_t)(n0 + n) * DD + kt + k);
            sw[k][n] = v.x; sw[k+1][n] = v.y;
        }
        __syncthreads();
#pragma unroll
        for (int k = 0; k < 16; k++) {
            float a0 = sx[k][tm0], a1 = sx[k][tm0+1], a2 = sx[k][tm0+2], a3 = sx[k][tm0+3];
            float b0 = sw[k][tn0], b1 = sw[k][tn0+1];
            acc[0][0] += a0*b0; acc[0][1] += a0*b1;
            acc[1][0] += a1*b0; acc[1][1] += a1*b1;
            acc[2][0] += a2*b0; acc[2][1] += a2*b1;
            acc[3][0] += a3*b0; acc[3][1] += a3*b1;
        }
        __syncthreads();
    }
#pragma unroll
    for (int q = 0; q < 4; q++)
#pragma unroll
        for (int r = 0; r < 2; r++) {
            int m = m0 + tm0 + q, n = n0 + tn0 + r;
            float v = acc[q][r];
            g_emb [m*EE + n] = v;
            g_wemb[m*EE + n] = v * Wo[n];
        }
}

// ---------------- Kernel 2: GX = emb @ Wih^T + bih (both GRUs) ----------------
__global__ __launch_bounds__(256) void gx_kernel(
    const float* __restrict__ Wih_a, const float* __restrict__ Wih_b,
    const float* __restrict__ bih_a, const float* __restrict__ bih_b)
{
    __shared__ float se [16][68];
    __shared__ float sw2[16][68];
    int tid = threadIdx.x;
    int m0 = blockIdx.x * 64;
    int n0 = blockIdx.y * 64;
    int tx = tid & 15, ty = tid >> 4;
    int tm0 = tx * 4, tn0 = ty * 4;

    const float* W; const float* bi; float* out; int nb;
    if (n0 < GG) { W = Wih_a; bi = bih_a; out = g_GXa; nb = n0; }
    else         { W = Wih_b; bi = bih_b; out = g_GXb; nb = n0 - GG; }

    float acc[4][4];
#pragma unroll
    for (int q = 0; q < 4; q++)
#pragma unroll
        for (int r = 0; r < 4; r++) acc[q][r] = 0.f;

    for (int kt = 0; kt < EE; kt += 16) {
        {
            int e = tid * 4; int m = e >> 4; int k = e & 15;
            float4 v = *(const float4*)(g_emb + (size_t)(m0 + m) * EE + kt + k);
            se[k][m] = v.x; se[k+1][m] = v.y; se[k+2][m] = v.z; se[k+3][m] = v.w;
        }
        {
            int e = tid * 4; int n = e >> 4; int k = e & 15;
            float4 v = *(const float4*)(W + (size_t)(nb + n) * EE + kt + k);
            sw2[k][n] = v.x; sw2[k+1][n] = v.y; sw2[k+2][n] = v.z; sw2[k+3][n] = v.w;
        }
        __syncthreads();
#pragma unroll
        for (int k = 0; k < 16; k++) {
            float a[4], b[4];
#pragma unroll
            for (int q = 0; q < 4; q++) a[q] = se[k][tm0+q];
#pragma unroll
            for (int r = 0; r < 4; r++) b[r] = sw2[k][tn0+r];
#pragma unroll
            for (int q = 0; q < 4; q++)
#pragma unroll
                for (int r = 0; r < 4; r++) acc[q][r] += a[q]*b[r];
        }
        __syncthreads();
    }
#pragma unroll
    for (int q = 0; q < 4; q++)
#pragma unroll
        for (int r = 0; r < 4; r++) {
            int m = m0 + tm0 + q, n = nb + tn0 + r;
            out[(size_t)m*GG + n] = acc[q][r] + bi[n];
        }
}

// ---------------- Kernel 3: persistent GRU scan (full-dot, 1 BAR/step) --------
// 256 threads: warp w covers units u = w*16 + (lane>>1); parity = lane&1 picks
// seqs 0-3 or 4-7. Thread computes FULL 128-h dots for r,z,n of its unit over
// its 4 seqs — no partial exchange; P2 is thread-local (h_old in registers).
// h double-buffered -> one __syncthreads per step.
__global__ __launch_bounds__(256, 1) void scan_kernel(
    const float* __restrict__ Whh_a, const float* __restrict__ Whh_b,
    const float* __restrict__ bhh_a, const float* __restrict__ bhh_b,
    int RA, int Rtot)
{
    extern __shared__ float smem[];
    float* shv = smem + OFF_H;

    unsigned sbase;
    asm("{ .reg .u64 t; cvta.to.shared.u64 t, %1; cvt.u32.u64 %0, t; }"
        : "=r"(sbase) : "l"(smem));
    unsigned shH = sbase + OFF_H * 4;      // h buffers: 2 x (8 x 132 floats)

    int tid = threadIdx.x;
    int lane = tid & 31, w = tid >> 5;
    int u = (w << 4) + (lane >> 1);
    int parity = lane & 1;
    int sqb = parity * 4;                  // my 4 seqs: sqb..sqb+3
    bool roleA = (blockIdx.x < RA);
    int rc = roleA ? blockIdx.x : blockIdx.x - RA;
    int R  = roleA ? RA : (Rtot - RA);

    const float* Whh = roleA ? Whh_a : Whh_b;
    const float* bhh = roleA ? bhh_a : bhh_b;
    const float* GX  = roleA ? g_GXa : g_GXb;
    float* HS        = roleA ? g_hsa : g_hsb;

    // stage all weight pairs into SMEM, ull2 entries e = (g*32+pp)*128 + u
    {
        const ull* W2 = (const ull*)Whh;
        ull* sz = (ull*)smem;
        for (int e = tid; e < 12288; e += 256) {
            int uu = e & 127;
            int pp = (e >> 7) & 31;
            int g  = e >> 12;
            const ull* src = W2 + (size_t)(g*128 + uu)*64 + 2*pp;
            sz[2*e]   = src[0];
            sz[2*e+1] = src[1];
        }
    }
    float bhr = bhh[u], bhz = bhh[128 + u], bhn = bhh[256 + u];

    unsigned wbR = sbase + (unsigned)u * 16;     // + pp*2048
    unsigned wbZ = wbR + 65536;
    unsigned wbN = wbZ + 65536;
    __syncthreads();

    for (int mIdx = 0;; mIdx++) {
        int g = mIdx*R + ((mIdx & 1) ? (R - 1 - rc) : rc);   // snake
        if (g >= NG8) break;

        int i  = 127 - (g >> 1);      // longest-first
        int b0 = (g & 1) * 8;

        __syncthreads();              // protect buffers vs previous group
        for (int idx = tid; idx < 8*132; idx += 256) shv[idx] = 0.f;  // buf0
        __syncthreads();

        float hold[4];
#pragma unroll
        for (int ss = 0; ss < 4; ss++) hold[ss] = 0.f;

        for (int k = 0; k <= i; k++) {
            int j = i - k;
            // gi prefetch for my 4 seqs (L2-resident; hidden under P1)
            float gir[4], giz[4], gin[4];
#pragma unroll
            for (int ss = 0; ss < 4; ss++) {
                const float* p = GX + (size_t)((b0 + sqb + ss)*TT + j)*GG + u;
                gir[ss] = __ldg(p);
                giz[ss] = __ldg(p + 128);
                gin[ss] = __ldg(p + 256);
            }

            // ---- P1: full dots, 3 gates x 4 seqs over all 128 h ----
            unsigned hb = shH + (unsigned)((k & 1) * 8*132) * 4
                              + (unsigned)sqb * 528;
            ull ar[4], az[4], an[4];
#pragma unroll
            for (int ss = 0; ss < 4; ss++) { ar[ss] = 0; az[ss] = 0; an[ss] = 0; }
#pragma unroll
            for (int pp = 0; pp < 32; pp++) {
                ull wr0, wr1, wz0, wz1, wn0, wn1;
                lds128v(wbR + (unsigned)pp*2048, wr0, wr1);
                lds128v(wbZ + (unsigned)pp*2048, wz0, wz1);
                lds128v(wbN + (unsigned)pp*2048, wn0, wn1);
#pragma unroll
                for (int ss = 0; ss < 4; ss++) {
                    ull p0, p1;
                    lds128v(hb + (unsigned)(ss*528 + pp*16), p0, p1);
                    ffma2(ar[ss], wr0, p0); ffma2(ar[ss], wr1, p1);
                    ffma2(az[ss], wz0, p0); ffma2(az[ss], wz1, p1);
                    ffma2(an[ss], wn0, p0); ffma2(an[ss], wn1, p1);
                }
            }

            // ---- P2: thread-local GRU update (writes buf (k+1)&1) ----
            int bufn = ((k + 1) & 1) * 8 * 132;
#pragma unroll
            for (int ss = 0; ss < 4; ss++) {
                int s = sqb + ss;
                float fr = pairsum(ar[ss]) + gir[ss] + bhr;
                float fz = pairsum(az[ss]) + giz[ss] + bhz;
                float fn = pairsum(an[ss]) + bhn;
                float rr = 0.5f + 0.5f * tanhhw(0.5f * fr);
                float zz = 0.5f + 0.5f * tanhhw(0.5f * fz);
                float nn = tanhhw(gin[ss] + rr * fn);
                float h2 = (1.f - zz)*nn + zz*hold[ss];
                hold[ss] = h2;
                shv[bufn + s*132 + u] = h2;
                HS[((size_t)k*NSEQ + (b0 + s)*TT + i)*HHN + u] = h2;
            }
            __syncthreads();
        } // k
    } // groups
}

// ---------------- Kernel 4: pre_alpha = 0.5*Wa·h_a + ba ----------------
__global__ __launch_bounds__(256) void alpha_kernel(
    const float* __restrict__ Wa, const float* __restrict__ ba)
{
    int r = blockIdx.x * 8 + (threadIdx.x >> 5);   // (k,n) flat
    int lane = threadIdx.x & 31;
    int k = r >> 11, n = r & 2047, i = n & 127;
    if (k > i) return;
    const float4 hv = *(const float4*)(g_hsa + ((size_t)k*NSEQ + n)*HHN + lane*4);
    const float4 wv = *(const float4*)(Wa + lane*4);
    float p = 0.5f*(hv.x*wv.x + hv.y*wv.y + hv.z*wv.z + hv.w*wv.w);
#pragma unroll
    for (int o = 16; o > 0; o >>= 1)
        p += __shfl_xor_sync(0xffffffffu, p, o);
    if (lane == 0) g_pa[(size_t)n*TT + k] = p + ba[0];
}

// ---------------- Kernel 5: beta GEMM + wemb dot -> s[n][k] (f32x2) ----------------
__global__ __launch_bounds__(256) void beta_kernel(
    const float* __restrict__ Wb, const float* __restrict__ bb)
{
    int k  = blockIdx.x;          // 0..127
    int nb = blockIdx.y;          // 0..31
    int i0 = (nb & 1) * 64;
    if (i0 + 63 < k) return;
    int n0 = nb * 64;
    int b  = n0 >> 7;

    __shared__ float shh[16][68];
    __shared__ float sww[16][132];
    __shared__ float red[64][17];

    int tid = threadIdx.x;
    int tx = tid & 15, ty = tid >> 4;
    int r0 = tx * 4, e0 = ty * 8;

    const float* hb = g_hsb + ((size_t)k*NSEQ + n0)*HHN;

    ull acc2[4][4];
#pragma unroll
    for (int q = 0; q < 4; q++)
#pragma unroll
        for (int e = 0; e < 4; e++) acc2[q][e] = 0;

    for (int kt = 0; kt < HHN; kt += 16) {
        {
            int e = tid * 4; int rr = e >> 4; int h = e & 15;
            float4 v = *(const float4*)(hb + (size_t)rr*HHN + kt + h);
            shh[h][rr] = v.x; shh[h+1][rr] = v.y; shh[h+2][rr] = v.z; shh[h+3][rr] = v.w;
        }
        {
            int e2 = tid * 8; int ee = e2 >> 4; int h = e2 & 15;
            float4 v0 = *(const float4*)(Wb + (size_t)ee*HHN + kt + h);
            float4 v1 = *(const float4*)(Wb + (size_t)ee*HHN + kt + h + 4);
            sww[h  ][ee] = 0.5f*v0.x; sww[h+1][ee] = 0.5f*v0.y;
            sww[h+2][ee] = 0.5f*v0.z; sww[h+3][ee] = 0.5f*v0.w;
            sww[h+4][ee] = 0.5f*v1.x; sww[h+5][ee] = 0.5f*v1.y;
            sww[h+6][ee] = 0.5f*v1.z; sww[h+7][ee] = 0.5f*v1.w;
        }
        __syncthreads();
#pragma unroll
        for (int kk = 0; kk < 16; kk++) {
            ull av[4], bv[4];
#pragma unroll
            for (int q = 0; q < 4; q++) av[q] = dup2(shh[kk][r0+q]);
            const ull* bp = (const ull*)&sww[kk][e0];
#pragma unroll
            for (int e = 0; e < 4; e++) bv[e] = bp[e];
#pragma unroll
            for (int q = 0; q < 4; q++)
#pragma unroll
                for (int e = 0; e < 4; e++) ffma2(acc2[q][e], av[q], bv[e]);
        }
        __syncthreads();
    }

    float bbv[8];
#pragma unroll
    for (int e = 0; e < 8; e++) bbv[e] = bb[e0 + e];

#pragma unroll
    for (int q = 0; q < 4; q++) {
        int n = n0 + r0 + q;
        int i = n & 127;
        int j = i - k;
        const float* wm = g_wemb + ((size_t)b*TT + (j >= 0 ? j : 0))*EE + e0;
        float p = 0.f;
#pragma unroll
        for (int e = 0; e < 4; e++) {
            float lo = __uint_as_float((unsigned)acc2[q][e]);
            float hi = __uint_as_float((unsigned)(acc2[q][e] >> 32));
            p += tanhhw(lo + bbv[2*e])   * wm[2*e];
            p += tanhhw(hi + bbv[2*e+1]) * wm[2*e+1];
        }
        red[r0 + q][ty] = p;
    }
    __syncthreads();
    if (tid < 64) {
        float v = 0.f;
#pragma unroll
        for (int t = 0; t < 16; t++) v += red[tid][t];
        int n = n0 + tid;
        int i = n & 127;
        if (k <= i) g_sv[(size_t)n*TT + k] = v;
    }
}

// ---------------- Kernel 6: masked softmax combine ----------------
__global__ __launch_bounds__(256) void combine_kernel(
    const float* __restrict__ bo, float* __restrict__ out)
{
    int w = blockIdx.x * 8 + (threadIdx.x >> 5);
    int lane = threadIdx.x & 31;
    if (w >= NSEQ) return;
    int i = w & 127;
    float num = 0.f, den = 0.f;
    for (int k = lane; k <= i; k += 32) {
        float ev = __expf(g_pa[(size_t)w*TT + k]);
        num += ev * g_sv[(size_t)w*TT + k];
        den += ev;
    }
#pragma unroll
    for (int o = 16; o > 0; o >>= 1) {
        num += __shfl_xor_sync(0xffffffffu, num, o);
        den += __shfl_xor_sync(0xffffffffu, den, o);
    }
    if (lane == 0) out[w] = num / den + bo[0];
}

// ---------------- launch ----------------
extern "C" void kernel_launch(void* const* d_in, const int* in_sizes, int n_in,
                              void* d_out, int out_size)
{
    const float* x     = (const float*)d_in[0];
    const float* Wemb  = (const float*)d_in[1];
    const float* Wih_a = (const float*)d_in[2];
    const float* Whh_a = (const float*)d_in[3];
    const float* bih_a = (const float*)d_in[4];
    const float* bhh_a = (const float*)d_in[5];
    const float* Wa    = (const float*)d_in[6];
    const float* ba    = (const float*)d_in[7];
    const float* Wih_b = (const float*)d_in[8];
    const float* Whh_b = (const float*)d_in[9];
    const float* bih_b = (const float*)d_in[10];
    const float* bhh_b = (const float*)d_in[11];
    const float* Wb    = (const float*)d_in[12];
    const float* bb    = (const float*)d_in[13];
    const float* Wo    = (const float*)d_in[14];
    const float* bo    = (const float*)d_in[15];
    float* out = (float*)d_out;

    int dev = 0;
    cudaGetDevice(&dev);
    int sms = 148;
    cudaDeviceGetAttribute(&sms, cudaDevAttrMultiProcessorCount, dev);
    int RA = sms / 2;

    size_t smem_bytes = (size_t)SMEM_FLOATS * sizeof(float);
    cudaFuncSetAttribute(scan_kernel,
                         cudaFuncAttributeMaxDynamicSharedMemorySize,
                         (int)smem_bytes);

    dummy_kernel<<<1, 32>>>();
    emb_kernel<<<dim3(32, 4), 256>>>(x, Wemb, Wo);
    gx_kernel<<<dim3(32, 12), 256>>>(Wih_a, Wih_b, bih_a, bih_b);
    scan_kernel<<<sms, 256, smem_bytes>>>(Whh_a, Whh_b, bhh_a, bhh_b, RA, sms);
    alpha_kernel<<<(NSEQ*TT)/8, 256>>>(Wa, ba);
    beta_kernel<<<dim3(TT, NSEQ/64), 256>>>(Wb, bb);
    combine_kernel<<<NSEQ/8, 256>>>(bo, out);
}